// round 1
// baseline (speedup 1.0000x reference)
#include <cuda_runtime.h>
#include <math.h>

// ---------------- scratch (static device allocations are allowed) ----------
// Q, K, V, O: [8192, 1024] fp32 each (32 MB each)
// S: [4, 2048, 2048] fp32 (64 MB)
__device__ float g_Q[8192 * 1024];
__device__ float g_K[8192 * 1024];
__device__ float g_V[8192 * 1024];
__device__ float g_O[8192 * 1024];
__device__ float g_S[4LL * 2048 * 2048];

// ---------------------------------------------------------------------------
// Tiled SGEMM: C[M,N] = A[M,K] * B + (bias) , optionally * scale
//   BT = true : B stored as [N,K]  (dot of rows; torch Linear weight / K^T)
//   BT = false: B stored as [K,N]
// 128x128 block tile, BK=8, 256 threads, 8x8 per-thread micro-tile.
// All dims are multiples of 128 (M in {8192,2048}, N in {1024,2048}, K in
// {1024,2048}), so no bounds checks.
// grid.z = batch; sA/sB/sC are per-batch element strides (0 for unbatched).
// ---------------------------------------------------------------------------
template <bool BT, bool BIAS, bool SCALE>
__global__ __launch_bounds__(256, 2) void gemm128(
    const float* __restrict__ A, const float* __restrict__ Bm,
    const float* __restrict__ bias, float* __restrict__ C,
    int M, int N, int K, float scale,
    long long sA, long long sB, long long sC)
{
    const long long bz = blockIdx.z;
    A  += bz * sA;
    Bm += bz * sB;
    C  += bz * sC;

    __shared__ float As[8][128];
    __shared__ float Bs[8][128];

    const int t  = threadIdx.x;
    const int tx = t & 15;      // 0..15 -> n
    const int ty = t >> 4;      // 0..15 -> m
    const int m0 = blockIdx.y * 128;
    const int n0 = blockIdx.x * 128;

    // A tile load mapping: 128 rows x 2 float4 quads
    const int arow = t >> 1;
    const int ac4  = (t & 1) * 4;
    const float* Aptr = A + (long long)(m0 + arow) * K + ac4;

    // B tile load mapping
    const float* Bptr;
    int br, bc;
    if (BT) {                 // B: [N,K], same pattern as A
        br = t >> 1;          // n within tile
        bc = (t & 1) * 4;     // k quad
        Bptr = Bm + (long long)(n0 + br) * K + bc;
    } else {                  // B: [K,N], 8 rows x 32 float4 quads
        br = t >> 5;          // k within tile (0..7)
        bc = (t & 31) * 4;    // n within tile
        Bptr = Bm + (long long)br * N + n0 + bc;
    }

    float acc[8][8];
#pragma unroll
    for (int i = 0; i < 8; i++)
#pragma unroll
        for (int j = 0; j < 8; j++) acc[i][j] = 0.0f;

    for (int k0 = 0; k0 < K; k0 += 8) {
        float4 av = *(const float4*)(Aptr + k0);
        float4 bv;
        if (BT) bv = *(const float4*)(Bptr + k0);
        else    bv = *(const float4*)(Bptr + (long long)k0 * N);

        __syncthreads();   // previous iteration's compute done

        As[ac4 + 0][arow] = av.x;
        As[ac4 + 1][arow] = av.y;
        As[ac4 + 2][arow] = av.z;
        As[ac4 + 3][arow] = av.w;
        if (BT) {
            Bs[bc + 0][br] = bv.x;
            Bs[bc + 1][br] = bv.y;
            Bs[bc + 2][br] = bv.z;
            Bs[bc + 3][br] = bv.w;
        } else {
            *(float4*)&Bs[br][bc] = bv;
        }
        __syncthreads();

#pragma unroll
        for (int k = 0; k < 8; k++) {
            float a[8], b[8];
            *(float4*)(a + 0) = *(const float4*)&As[k][ty * 4];
            *(float4*)(a + 4) = *(const float4*)&As[k][64 + ty * 4];
            *(float4*)(b + 0) = *(const float4*)&Bs[k][tx * 4];
            *(float4*)(b + 4) = *(const float4*)&Bs[k][64 + tx * 4];
#pragma unroll
            for (int i = 0; i < 8; i++)
#pragma unroll
                for (int j = 0; j < 8; j++)
                    acc[i][j] = fmaf(a[i], b[j], acc[i][j]);
        }
    }

    // epilogue: rows {ih*64 + ty*4 + i}, cols {jh*64 + tx*4 + j}
#pragma unroll
    for (int ih = 0; ih < 2; ih++) {
#pragma unroll
        for (int i = 0; i < 4; i++) {
            const int row = m0 + ih * 64 + ty * 4 + i;
#pragma unroll
            for (int jh = 0; jh < 2; jh++) {
                const int col = n0 + jh * 64 + tx * 4;
                float4 v;
                v.x = acc[ih * 4 + i][jh * 4 + 0];
                v.y = acc[ih * 4 + i][jh * 4 + 1];
                v.z = acc[ih * 4 + i][jh * 4 + 2];
                v.w = acc[ih * 4 + i][jh * 4 + 3];
                if (SCALE) {
                    v.x *= scale; v.y *= scale; v.z *= scale; v.w *= scale;
                }
                if (BIAS) {
                    float4 bb = *(const float4*)&bias[col];
                    v.x += bb.x; v.y += bb.y; v.z += bb.z; v.w += bb.w;
                }
                *(float4*)&C[(long long)row * N + col] = v;
            }
        }
    }
}

// ---------------------------------------------------------------------------
// Row softmax over T=2048 elements; one block per row; row cached in smem
// (single gmem read + single write).
// ---------------------------------------------------------------------------
__global__ __launch_bounds__(256) void softmax_row(float* __restrict__ S, int T)
{
    __shared__ float buf[2048];
    __shared__ float red[256];

    const long long row = blockIdx.x;
    float* r = S + row * T;
    const int t = threadIdx.x;

    float m = -1e30f;
    for (int i = t * 4; i < T; i += 1024) {
        float4 v = *(const float4*)&r[i];
        *(float4*)&buf[i] = v;
        m = fmaxf(m, fmaxf(fmaxf(v.x, v.y), fmaxf(v.z, v.w)));
    }
    red[t] = m;
    __syncthreads();
    for (int s = 128; s > 0; s >>= 1) {
        if (t < s) red[t] = fmaxf(red[t], red[t + s]);
        __syncthreads();
    }
    m = red[0];
    __syncthreads();   // everyone has read red[0] before reuse

    float sum = 0.0f;
    for (int i = t * 4; i < T; i += 1024) {
        float4 v = *(const float4*)&buf[i];
        v.x = expf(v.x - m);
        v.y = expf(v.y - m);
        v.z = expf(v.z - m);
        v.w = expf(v.w - m);
        sum += v.x + v.y + v.z + v.w;
        *(float4*)&buf[i] = v;
    }
    red[t] = sum;
    __syncthreads();
    for (int s = 128; s > 0; s >>= 1) {
        if (t < s) red[t] += red[t + s];
        __syncthreads();
    }
    const float inv = 1.0f / red[0];

    for (int i = t * 4; i < T; i += 1024) {
        float4 v = *(const float4*)&buf[i];
        v.x *= inv; v.y *= inv; v.z *= inv; v.w *= inv;
        *(float4*)&r[i] = v;
    }
}

// ---------------------------------------------------------------------------
extern "C" void kernel_launch(void* const* d_in, const int* in_sizes, int n_in,
                              void* d_out, int out_size)
{
    (void)in_sizes; (void)n_in; (void)out_size;

    const float* x  = (const float*)d_in[0];
    const float* Wq = (const float*)d_in[1];
    const float* bq = (const float*)d_in[2];
    const float* Wk = (const float*)d_in[3];
    const float* bk = (const float*)d_in[4];
    const float* Wv = (const float*)d_in[5];
    const float* bv = (const float*)d_in[6];
    const float* Wo = (const float*)d_in[7];
    const float* bo = (const float*)d_in[8];
    float* out = (float*)d_out;

    float *Q, *K, *V, *O, *S;
    cudaGetSymbolAddress((void**)&Q, g_Q);
    cudaGetSymbolAddress((void**)&K, g_K);
    cudaGetSymbolAddress((void**)&V, g_V);
    cudaGetSymbolAddress((void**)&O, g_O);
    cudaGetSymbolAddress((void**)&S, g_S);

    const int B = 4, T = 2048, D = 1024;
    const int M = B * T;                      // 8192
    const float scale = 0.03125f;             // 1/sqrt(1024)

    dim3 th(256);
    dim3 gp(D / 128, M / 128, 1);             // 8 x 64   projections / output
    dim3 gs(T / 128, T / 128, B);             // 16 x 16 x 4  scores
    dim3 gv(D / 128, T / 128, B);             // 8 x 16 x 4   P @ V

    const long long sTD = (long long)T * D;   // per-batch stride of Q/K/V/O
    const long long sTT = (long long)T * T;   // per-batch stride of S

    // Q/K/V projections: [8192,1024] = x[8192,1024] @ W[1024,1024]^T + b
    gemm128<true,  true,  false><<<gp, th>>>(x, Wq, bq, Q, M, D, D, 1.0f, 0, 0, 0);
    gemm128<true,  true,  false><<<gp, th>>>(x, Wk, bk, K, M, D, D, 1.0f, 0, 0, 0);
    gemm128<true,  true,  false><<<gp, th>>>(x, Wv, bv, V, M, D, D, 1.0f, 0, 0, 0);

    // scores: S[b] = (Q[b] @ K[b]^T) / 32
    gemm128<true,  false, true ><<<gs, th>>>(Q, K, nullptr, S, T, T, D, scale,
                                             sTD, sTD, sTT);

    // softmax over last dim
    softmax_row<<<B * T, 256>>>(S, T);

    // O[b] = S[b] @ V[b]
    gemm128<false, false, false><<<gv, th>>>(S, V, nullptr, O, T, D, T, 1.0f,
                                             sTT, sTD, sTD);

    // out = O @ Wo^T + bo
    gemm128<true,  true,  false><<<gp, th>>>(O, Wo, bo, out, M, D, D, 1.0f, 0, 0, 0);
}

// round 3
// speedup vs baseline: 3.3288x; 3.3288x over previous
#include <cuda_runtime.h>
#include <cstdint>
#include <math.h>

// ------------------------------ scratch ------------------------------------
__device__ float g_Q [8192 * 1024];
__device__ float g_K [8192 * 1024];
__device__ float g_V [8192 * 1024];
__device__ float g_Vt[8192 * 1024];
__device__ float g_O [8192 * 1024];
__device__ float g_S [4LL * 2048 * 2048];

// ------------------------------ helpers ------------------------------------
__device__ __forceinline__ uint32_t smem_u32(const void* p) {
    uint32_t a;
    asm("{ .reg .u64 t; cvta.to.shared.u64 t, %1; cvt.u32.u64 %0, t; }"
        : "=r"(a) : "l"(p));
    return a;
}
__device__ __forceinline__ uint32_t f2tf32(uint32_t f) {
    uint32_t r;
    asm("cvt.rna.tf32.f32 %0, %1;" : "=r"(r) : "r"(f));
    return r;
}
__device__ __forceinline__ void ldsm4(uint32_t& r0, uint32_t& r1,
                                      uint32_t& r2, uint32_t& r3, uint32_t a) {
    asm volatile("ldmatrix.sync.aligned.m8n8.x4.shared.b16 {%0,%1,%2,%3}, [%4];"
                 : "=r"(r0), "=r"(r1), "=r"(r2), "=r"(r3) : "r"(a));
}
__device__ __forceinline__ void mma_tf32(float* d, const uint32_t* a,
                                         const uint32_t* b) {
    asm volatile(
        "mma.sync.aligned.m16n8k8.row.col.f32.tf32.tf32.f32 "
        "{%0,%1,%2,%3}, {%4,%5,%6,%7}, {%8,%9}, {%0,%1,%2,%3};"
        : "+f"(d[0]), "+f"(d[1]), "+f"(d[2]), "+f"(d[3])
        : "r"(a[0]), "r"(a[1]), "r"(a[2]), "r"(a[3]), "r"(b[0]), "r"(b[1]));
}
#define CP_ASYNC16(s, g) \
    asm volatile("cp.async.cg.shared.global [%0], [%1], 16;" :: "r"(s), "l"(g))
#define CP_COMMIT()  asm volatile("cp.async.commit_group;" ::: "memory")
#define CP_WAIT1()   asm volatile("cp.async.wait_group 1;" ::: "memory")

// ------------------------------ GEMM ---------------------------------------
// C[M,N] = A[M,K] @ B[N,K]^T   (both K-major fp32; tf32 MMA, fp32 accumulate)
static constexpr int BM = 128, BN = 128, BK = 32, STAGES = 3;
static constexpr int AB_BYTES    = BM * BK * 4;            // 16384
static constexpr int STAGE_BYTES = 2 * AB_BYTES;           // 32768
static constexpr int SMEM_TOTAL  = STAGES * STAGE_BYTES;   // 98304

// swizzled byte offset of (row, 16B-quad q) inside a [rows][32 floats] tile
__device__ __forceinline__ uint32_t swz(int r, int q) {
    return (uint32_t)(r * 128 + ((q ^ (r & 7)) << 4));
}

template <bool BIAS, bool SCALE>
__global__ __launch_bounds__(256, 2) void tc_gemm(
    const float* __restrict__ A, const float* __restrict__ Bm,
    const float* __restrict__ bias, float* __restrict__ C,
    int M, int N, int K, float scale,
    long long sA, long long sB, long long sC)
{
    extern __shared__ __align__(1024) char smem[];
    const uint32_t sb = smem_u32(smem);

    const int tid  = threadIdx.x;
    const int lane = tid & 31;
    const int wid  = tid >> 5;
    const int wm   = (wid >> 2) * 64;   // warp m offset in tile
    const int wn   = (wid & 3) * 32;    // warp n offset in tile

    const long long bz = blockIdx.z;
    A  += bz * sA;
    Bm += bz * sB;
    C  += bz * sC;
    const int m0 = blockIdx.y * BM;
    const int n0 = blockIdx.x * BN;
    const int nchunks = K / BK;

    // loader mapping: thread i handles 16B quads i, i+256, ... of [A|B] tile
    // quad idx -> row = idx>>3, q = idx&7
    // ldmatrix source rows (per thread): midx = lane>>3, l7 = lane&7
    const int midx = lane >> 3, l7 = lane & 7;
    int aR[4];
#pragma unroll
    for (int mi = 0; mi < 4; mi++) aR[mi] = wm + mi * 16 + ((midx & 1) << 3) + l7;
    const int aKH = midx >> 1;
    int bR[2];
#pragma unroll
    for (int n2 = 0; n2 < 2; n2++) bR[n2] = wn + n2 * 16 + ((midx >> 1) << 3) + l7;
    const int bKH = midx & 1;

    float acc[4][4][4];
#pragma unroll
    for (int mi = 0; mi < 4; mi++)
#pragma unroll
        for (int ni = 0; ni < 4; ni++)
#pragma unroll
            for (int j = 0; j < 4; j++) acc[mi][ni][j] = 0.0f;

    // ---- async copy of chunk c into stage c%3 ----
    auto issue = [&](int c) {
        if (c < nchunks) {
            const int s = c % STAGES;
            const uint32_t As = sb + s * STAGE_BYTES;
            const uint32_t Bs = As + AB_BYTES;
            const int k0 = c * BK;
#pragma unroll
            for (int i = tid; i < 2048; i += 256) {
                const int idx = i & 1023;
                const int r = idx >> 3, q = idx & 7;
                if (i < 1024) {
                    CP_ASYNC16(As + swz(r, q),
                               A + (long long)(m0 + r) * K + k0 + q * 4);
                } else {
                    CP_ASYNC16(Bs + swz(r, q),
                               Bm + (long long)(n0 + r) * K + k0 + q * 4);
                }
            }
        }
        CP_COMMIT();
    };

    issue(0);
    issue(1);

    for (int c = 0; c < nchunks; c++) {
        CP_WAIT1();
        __syncthreads();
        issue(c + 2);

        const int s = c % STAGES;
        const uint32_t As = sb + s * STAGE_BYTES;
        const uint32_t Bs = As + AB_BYTES;

#pragma unroll
        for (int kk = 0; kk < 4; kk++) {
            uint32_t aF[4][4], bF[4][2];
#pragma unroll
            for (int mi = 0; mi < 4; mi++) {
                ldsm4(aF[mi][0], aF[mi][1], aF[mi][2], aF[mi][3],
                      As + swz(aR[mi], kk * 2 + aKH));
#pragma unroll
                for (int j = 0; j < 4; j++) aF[mi][j] = f2tf32(aF[mi][j]);
            }
#pragma unroll
            for (int n2 = 0; n2 < 2; n2++) {
                uint32_t r0, r1, r2, r3;
                ldsm4(r0, r1, r2, r3, Bs + swz(bR[n2], kk * 2 + bKH));
                bF[n2 * 2 + 0][0] = f2tf32(r0);
                bF[n2 * 2 + 0][1] = f2tf32(r1);
                bF[n2 * 2 + 1][0] = f2tf32(r2);
                bF[n2 * 2 + 1][1] = f2tf32(r3);
            }
#pragma unroll
            for (int mi = 0; mi < 4; mi++)
#pragma unroll
                for (int ni = 0; ni < 4; ni++)
                    mma_tf32(acc[mi][ni], aF[mi], bF[ni]);
        }
    }

    // ------------------ epilogue ------------------
    const int crow = lane >> 2;          // 0..7
    const int ccol = (lane & 3) * 2;     // 0,2,4,6
#pragma unroll
    for (int mi = 0; mi < 4; mi++) {
#pragma unroll
        for (int ni = 0; ni < 4; ni++) {
            const int col = n0 + wn + ni * 8 + ccol;
            float2 b2 = make_float2(0.f, 0.f);
            if (BIAS) b2 = *(const float2*)&bias[col];
#pragma unroll
            for (int h = 0; h < 2; h++) {
                const int row = m0 + wm + mi * 16 + crow + h * 8;
                float2 v;
                v.x = acc[mi][ni][h * 2 + 0];
                v.y = acc[mi][ni][h * 2 + 1];
                if (SCALE) { v.x *= scale; v.y *= scale; }
                if (BIAS)  { v.x += b2.x;  v.y += b2.y; }
                *(float2*)&C[(long long)row * N + col] = v;
            }
        }
    }
}

// ------------------------------ transpose ----------------------------------
__global__ __launch_bounds__(256) void transpose_TD(
    const float* __restrict__ V, float* __restrict__ Vt)
{
    __shared__ float tile[32][33];
    const long long b = blockIdx.z;
    const float* src = V + b * 2048LL * 1024;
    float* dst = Vt + b * 2048LL * 1024;
    const int x0 = blockIdx.x * 32;   // d
    const int y0 = blockIdx.y * 32;   // t
    const int tx = threadIdx.x & 31;
    const int ty = threadIdx.x >> 5;
#pragma unroll
    for (int i = 0; i < 32; i += 8)
        tile[ty + i][tx] = src[(long long)(y0 + ty + i) * 1024 + x0 + tx];
    __syncthreads();
#pragma unroll
    for (int i = 0; i < 32; i += 8)
        dst[(long long)(x0 + ty + i) * 2048 + y0 + tx] = tile[tx][ty + i];
}

// ------------------------------ softmax ------------------------------------
__global__ __launch_bounds__(256) void softmax_row(float* __restrict__ S, int T)
{
    __shared__ float buf[2048];
    __shared__ float red[256];
    const long long row = blockIdx.x;
    float* r = S + row * T;
    const int t = threadIdx.x;

    float m = -1e30f;
    for (int i = t * 4; i < T; i += 1024) {
        float4 v = *(const float4*)&r[i];
        *(float4*)&buf[i] = v;
        m = fmaxf(m, fmaxf(fmaxf(v.x, v.y), fmaxf(v.z, v.w)));
    }
    red[t] = m;
    __syncthreads();
    for (int s = 128; s > 0; s >>= 1) {
        if (t < s) red[t] = fmaxf(red[t], red[t + s]);
        __syncthreads();
    }
    m = red[0];
    __syncthreads();

    float sum = 0.0f;
    for (int i = t * 4; i < T; i += 1024) {
        float4 v = *(const float4*)&buf[i];
        v.x = expf(v.x - m); v.y = expf(v.y - m);
        v.z = expf(v.z - m); v.w = expf(v.w - m);
        sum += v.x + v.y + v.z + v.w;
        *(float4*)&buf[i] = v;
    }
    red[t] = sum;
    __syncthreads();
    for (int s = 128; s > 0; s >>= 1) {
        if (t < s) red[t] += red[t + s];
        __syncthreads();
    }
    const float inv = 1.0f / red[0];
    for (int i = t * 4; i < T; i += 1024) {
        float4 v = *(const float4*)&buf[i];
        v.x *= inv; v.y *= inv; v.z *= inv; v.w *= inv;
        *(float4*)&r[i] = v;
    }
}

// ------------------------------ launch -------------------------------------
extern "C" void kernel_launch(void* const* d_in, const int* in_sizes, int n_in,
                              void* d_out, int out_size)
{
    (void)in_sizes; (void)n_in; (void)out_size;
    const float* x  = (const float*)d_in[0];
    const float* Wq = (const float*)d_in[1];
    const float* bq = (const float*)d_in[2];
    const float* Wk = (const float*)d_in[3];
    const float* bk = (const float*)d_in[4];
    const float* Wv = (const float*)d_in[5];
    const float* bv = (const float*)d_in[6];
    const float* Wo = (const float*)d_in[7];
    const float* bo = (const float*)d_in[8];
    float* out = (float*)d_out;

    float *Q, *K, *V, *Vt, *O, *S;
    cudaGetSymbolAddress((void**)&Q,  g_Q);
    cudaGetSymbolAddress((void**)&K,  g_K);
    cudaGetSymbolAddress((void**)&V,  g_V);
    cudaGetSymbolAddress((void**)&Vt, g_Vt);
    cudaGetSymbolAddress((void**)&O,  g_O);
    cudaGetSymbolAddress((void**)&S,  g_S);

    const int B = 4, T = 2048, D = 1024;
    const int M = B * T;
    const float scale = 0.03125f;   // 1/sqrt(1024)
    const long long sTD = (long long)T * D;
    const long long sTT = (long long)T * T;

    cudaFuncSetAttribute(tc_gemm<true,  false>,
                         cudaFuncAttributeMaxDynamicSharedMemorySize, SMEM_TOTAL);
    cudaFuncSetAttribute(tc_gemm<false, true >,
                         cudaFuncAttributeMaxDynamicSharedMemorySize, SMEM_TOTAL);
    cudaFuncSetAttribute(tc_gemm<false, false>,
                         cudaFuncAttributeMaxDynamicSharedMemorySize, SMEM_TOTAL);

    dim3 th(256);
    dim3 gp(D / BN, M / BM, 1);     // 8 x 64      projections / output
    dim3 gs(T / BN, T / BM, B);     // 16 x 16 x 4 scores
    dim3 gv(D / BN, T / BM, B);     // 8 x 16 x 4  P @ V

    tc_gemm<true,  false><<<gp, th, SMEM_TOTAL>>>(x, Wq, bq, Q, M, D, D, 1.0f, 0, 0, 0);
    tc_gemm<true,  false><<<gp, th, SMEM_TOTAL>>>(x, Wk, bk, K, M, D, D, 1.0f, 0, 0, 0);
    tc_gemm<true,  false><<<gp, th, SMEM_TOTAL>>>(x, Wv, bv, V, M, D, D, 1.0f, 0, 0, 0);

    transpose_TD<<<dim3(D / 32, T / 32, B), 256>>>(V, Vt);

    tc_gemm<false, true ><<<gs, th, SMEM_TOTAL>>>(Q, K, nullptr, S, T, T, D, scale,
                                                  sTD, sTD, sTT);
    softmax_row<<<B * T, 256>>>(S, T);

    tc_gemm<false, false><<<gv, th, SMEM_TOTAL>>>(S, Vt, nullptr, O, T, D, T, 1.0f,
                                                  sTT, sTD, sTD);

    tc_gemm<true,  false><<<gp, th, SMEM_TOTAL>>>(O, Wo, bo, out, M, D, D, 1.0f, 0, 0, 0);
}

// round 4
// speedup vs baseline: 6.8185x; 2.0483x over previous
#include <cuda_runtime.h>
#include <cuda_fp16.h>
#include <cstdint>
#include <math.h>

// ------------------------------ scratch ------------------------------------
__device__ __half g_xh [8192 * 1024];
__device__ __half g_Wqh[1024 * 1024];
__device__ __half g_Wkh[1024 * 1024];
__device__ __half g_Wvh[1024 * 1024];
__device__ __half g_Woh[1024 * 1024];
__device__ __half g_Qh [8192 * 1024];
__device__ __half g_Kh [8192 * 1024];
__device__ __half g_Vh [8192 * 1024];
__device__ __half g_Vth[8192 * 1024];
__device__ __half g_Oh [8192 * 1024];
__device__ __half g_Ph [4LL * 2048 * 2048];
__device__ float  g_S  [4LL * 2048 * 2048];

// ------------------------------ helpers ------------------------------------
__device__ __forceinline__ uint32_t smem_u32(const void* p) {
    uint32_t a;
    asm("{ .reg .u64 t; cvta.to.shared.u64 t, %1; cvt.u32.u64 %0, t; }"
        : "=r"(a) : "l"(p));
    return a;
}
__device__ __forceinline__ void ldsm4(uint32_t& r0, uint32_t& r1,
                                      uint32_t& r2, uint32_t& r3, uint32_t a) {
    asm volatile("ldmatrix.sync.aligned.m8n8.x4.shared.b16 {%0,%1,%2,%3}, [%4];"
                 : "=r"(r0), "=r"(r1), "=r"(r2), "=r"(r3) : "r"(a));
}
__device__ __forceinline__ void mma_f16(float* d, const uint32_t* a,
                                        const uint32_t* b) {
    asm volatile(
        "mma.sync.aligned.m16n8k16.row.col.f32.f16.f16.f32 "
        "{%0,%1,%2,%3}, {%4,%5,%6,%7}, {%8,%9}, {%0,%1,%2,%3};"
        : "+f"(d[0]), "+f"(d[1]), "+f"(d[2]), "+f"(d[3])
        : "r"(a[0]), "r"(a[1]), "r"(a[2]), "r"(a[3]), "r"(b[0]), "r"(b[1]));
}
#define CP_ASYNC16(s, g) \
    asm volatile("cp.async.cg.shared.global [%0], [%1], 16;" :: "r"(s), "l"(g))
#define CP_COMMIT()  asm volatile("cp.async.commit_group;" ::: "memory")
#define CP_WAIT1()   asm volatile("cp.async.wait_group 1;" ::: "memory")

// ------------------------------ GEMM ---------------------------------------
// C[M,N] = A[M,K] @ B[N,K]^T   (half inputs, fp16 MMA, fp32 accumulate)
static constexpr int BM = 128, BN = 128, BK = 64, STAGES = 3;
static constexpr int AB_BYTES    = BM * BK * 2;            // 16384
static constexpr int STAGE_BYTES = 2 * AB_BYTES;           // 32768
static constexpr int SMEM_TOTAL  = STAGES * STAGE_BYTES;   // 98304

// swizzled byte offset of (row, 16B-quad q) in a [rows][64 halves] tile
__device__ __forceinline__ uint32_t swz(int r, int q) {
    return (uint32_t)(r * 128 + ((q ^ (r & 7)) << 4));
}

// OUTH: store C as half; otherwise float.
template <bool BIAS, bool SCALE, bool OUTH>
__global__ __launch_bounds__(256, 2) void tc_gemm(
    const __half* __restrict__ A, const __half* __restrict__ Bm,
    const float* __restrict__ bias, void* __restrict__ Cv,
    int M, int N, int K, float scale,
    long long sA, long long sB, long long sC)
{
    extern __shared__ __align__(1024) char smem[];
    const uint32_t sb = smem_u32(smem);

    const int tid  = threadIdx.x;
    const int lane = tid & 31;
    const int wid  = tid >> 5;
    const int wm   = (wid >> 2) * 64;
    const int wn   = (wid & 3) * 32;

    const long long bz = blockIdx.z;
    A  += bz * sA;
    Bm += bz * sB;
    const int m0 = blockIdx.y * BM;
    const int n0 = blockIdx.x * BN;
    const int nchunks = K / BK;

    const int midx = lane >> 3, l7 = lane & 7;
    int aR[4];
#pragma unroll
    for (int mi = 0; mi < 4; mi++) aR[mi] = wm + mi * 16 + ((midx & 1) << 3) + l7;
    const int aKH = midx >> 1;
    int bR[2];
#pragma unroll
    for (int n2 = 0; n2 < 2; n2++) bR[n2] = wn + n2 * 16 + ((midx >> 1) << 3) + l7;
    const int bKH = midx & 1;

    float acc[4][4][4];
#pragma unroll
    for (int mi = 0; mi < 4; mi++)
#pragma unroll
        for (int ni = 0; ni < 4; ni++)
#pragma unroll
            for (int j = 0; j < 4; j++) acc[mi][ni][j] = 0.0f;

    auto issue = [&](int c) {
        if (c < nchunks) {
            const int s = c % STAGES;
            const uint32_t As = sb + s * STAGE_BYTES;
            const uint32_t Bs = As + AB_BYTES;
            const int k0 = c * BK;
#pragma unroll
            for (int i = tid; i < 2048; i += 256) {
                const int idx = i & 1023;
                const int r = idx >> 3, q = idx & 7;
                if (i < 1024) {
                    CP_ASYNC16(As + swz(r, q),
                               A + (long long)(m0 + r) * K + k0 + q * 8);
                } else {
                    CP_ASYNC16(Bs + swz(r, q),
                               Bm + (long long)(n0 + r) * K + k0 + q * 8);
                }
            }
        }
        CP_COMMIT();
    };

    issue(0);
    issue(1);

    for (int c = 0; c < nchunks; c++) {
        CP_WAIT1();
        __syncthreads();
        issue(c + 2);

        const int s = c % STAGES;
        const uint32_t As = sb + s * STAGE_BYTES;
        const uint32_t Bs = As + AB_BYTES;

#pragma unroll
        for (int kk = 0; kk < 4; kk++) {        // 4 x k16
            uint32_t aF[4][4], bF[4][2];
#pragma unroll
            for (int mi = 0; mi < 4; mi++)
                ldsm4(aF[mi][0], aF[mi][1], aF[mi][2], aF[mi][3],
                      As + swz(aR[mi], kk * 2 + aKH));
#pragma unroll
            for (int n2 = 0; n2 < 2; n2++) {
                uint32_t r0, r1, r2, r3;
                ldsm4(r0, r1, r2, r3, Bs + swz(bR[n2], kk * 2 + bKH));
                bF[n2 * 2 + 0][0] = r0;
                bF[n2 * 2 + 0][1] = r1;
                bF[n2 * 2 + 1][0] = r2;
                bF[n2 * 2 + 1][1] = r3;
            }
#pragma unroll
            for (int mi = 0; mi < 4; mi++)
#pragma unroll
                for (int ni = 0; ni < 4; ni++)
                    mma_f16(acc[mi][ni], aF[mi], bF[ni]);
        }
    }

    // ------------------ epilogue ------------------
    const int crow = lane >> 2;
    const int ccol = (lane & 3) * 2;
#pragma unroll
    for (int mi = 0; mi < 4; mi++) {
#pragma unroll
        for (int ni = 0; ni < 4; ni++) {
            const int col = n0 + wn + ni * 8 + ccol;
            float2 b2 = make_float2(0.f, 0.f);
            if (BIAS) b2 = *(const float2*)&bias[col];
#pragma unroll
            for (int h = 0; h < 2; h++) {
                const int row = m0 + wm + mi * 16 + crow + h * 8;
                float vx = acc[mi][ni][h * 2 + 0];
                float vy = acc[mi][ni][h * 2 + 1];
                if (SCALE) { vx *= scale; vy *= scale; }
                if (BIAS)  { vx += b2.x;  vy += b2.y; }
                if (OUTH) {
                    __half2* C = (__half2*)((__half*)Cv + bz * sC);
                    C[((long long)row * N + col) >> 1] = __floats2half2_rn(vx, vy);
                } else {
                    float* C = (float*)Cv + bz * sC;
                    *(float2*)&C[(long long)row * N + col] = make_float2(vx, vy);
                }
            }
        }
    }
}

// ------------------------------ conversions --------------------------------
__global__ __launch_bounds__(256) void conv_f2h(const float* __restrict__ s,
                                                __half* __restrict__ d, int n)
{
    int i = (blockIdx.x * 256 + threadIdx.x) * 4;
    if (i < n) {
        float4 v = *(const float4*)&s[i];
        __half2 h0 = __floats2half2_rn(v.x, v.y);
        __half2 h1 = __floats2half2_rn(v.z, v.w);
        *(__half2*)&d[i]     = h0;
        *(__half2*)&d[i + 2] = h1;
    }
}

// Vth[b][d][t] = Vh[b][t][d]
__global__ __launch_bounds__(256) void transpose_h(
    const __half* __restrict__ V, __half* __restrict__ Vt)
{
    __shared__ __half tile[32][33];
    const long long b = blockIdx.z;
    const __half* src = V + b * 2048LL * 1024;
    __half* dst = Vt + b * 2048LL * 1024;
    const int x0 = blockIdx.x * 32;   // d
    const int y0 = blockIdx.y * 32;   // t
    const int tx = threadIdx.x & 31;
    const int ty = threadIdx.x >> 5;
#pragma unroll
    for (int i = 0; i < 32; i += 8)
        tile[ty + i][tx] = src[(long long)(y0 + ty + i) * 1024 + x0 + tx];
    __syncthreads();
#pragma unroll
    for (int i = 0; i < 32; i += 8)
        dst[(long long)(x0 + ty + i) * 2048 + y0 + tx] = tile[tx][ty + i];
}

// ------------------------------ softmax ------------------------------------
// read fp32 scores row, write normalized half row
__global__ __launch_bounds__(256) void softmax_row(
    const float* __restrict__ S, __half* __restrict__ P, int T)
{
    __shared__ float buf[2048];
    __shared__ float red[256];
    const long long row = blockIdx.x;
    const float* r = S + row * T;
    __half* o = P + row * T;
    const int t = threadIdx.x;

    float m = -1e30f;
    for (int i = t * 4; i < T; i += 1024) {
        float4 v = *(const float4*)&r[i];
        *(float4*)&buf[i] = v;
        m = fmaxf(m, fmaxf(fmaxf(v.x, v.y), fmaxf(v.z, v.w)));
    }
    red[t] = m;
    __syncthreads();
    for (int s = 128; s > 0; s >>= 1) {
        if (t < s) red[t] = fmaxf(red[t], red[t + s]);
        __syncthreads();
    }
    m = red[0];
    __syncthreads();

    float sum = 0.0f;
    for (int i = t * 4; i < T; i += 1024) {
        float4 v = *(const float4*)&buf[i];
        v.x = expf(v.x - m); v.y = expf(v.y - m);
        v.z = expf(v.z - m); v.w = expf(v.w - m);
        sum += v.x + v.y + v.z + v.w;
        *(float4*)&buf[i] = v;
    }
    red[t] = sum;
    __syncthreads();
    for (int s = 128; s > 0; s >>= 1) {
        if (t < s) red[t] += red[t + s];
        __syncthreads();
    }
    const float inv = 1.0f / red[0];
    for (int i = t * 4; i < T; i += 1024) {
        float4 v = *(const float4*)&buf[i];
        *(__half2*)&o[i]     = __floats2half2_rn(v.x * inv, v.y * inv);
        *(__half2*)&o[i + 2] = __floats2half2_rn(v.z * inv, v.w * inv);
    }
}

// ------------------------------ launch -------------------------------------
extern "C" void kernel_launch(void* const* d_in, const int* in_sizes, int n_in,
                              void* d_out, int out_size)
{
    (void)in_sizes; (void)n_in; (void)out_size;
    const float* x  = (const float*)d_in[0];
    const float* Wq = (const float*)d_in[1];
    const float* bq = (const float*)d_in[2];
    const float* Wk = (const float*)d_in[3];
    const float* bk = (const float*)d_in[4];
    const float* Wv = (const float*)d_in[5];
    const float* bv = (const float*)d_in[6];
    const float* Wo = (const float*)d_in[7];
    const float* bo = (const float*)d_in[8];
    float* out = (float*)d_out;

    __half *xh, *Wqh, *Wkh, *Wvh, *Woh, *Qh, *Kh, *Vh, *Vth, *Oh, *Ph;
    float* S;
    cudaGetSymbolAddress((void**)&xh,  g_xh);
    cudaGetSymbolAddress((void**)&Wqh, g_Wqh);
    cudaGetSymbolAddress((void**)&Wkh, g_Wkh);
    cudaGetSymbolAddress((void**)&Wvh, g_Wvh);
    cudaGetSymbolAddress((void**)&Woh, g_Woh);
    cudaGetSymbolAddress((void**)&Qh,  g_Qh);
    cudaGetSymbolAddress((void**)&Kh,  g_Kh);
    cudaGetSymbolAddress((void**)&Vh,  g_Vh);
    cudaGetSymbolAddress((void**)&Vth, g_Vth);
    cudaGetSymbolAddress((void**)&Oh,  g_Oh);
    cudaGetSymbolAddress((void**)&Ph,  g_Ph);
    cudaGetSymbolAddress((void**)&S,   g_S);

    const int B = 4, T = 2048, D = 1024;
    const int M = B * T;
    const float scale = 0.03125f;   // 1/sqrt(1024)
    const long long sTD = (long long)T * D;
    const long long sTT = (long long)T * T;

    cudaFuncSetAttribute(tc_gemm<true,  false, true >,
                         cudaFuncAttributeMaxDynamicSharedMemorySize, SMEM_TOTAL);
    cudaFuncSetAttribute(tc_gemm<false, true,  false>,
                         cudaFuncAttributeMaxDynamicSharedMemorySize, SMEM_TOTAL);
    cudaFuncSetAttribute(tc_gemm<false, false, true >,
                         cudaFuncAttributeMaxDynamicSharedMemorySize, SMEM_TOTAL);
    cudaFuncSetAttribute(tc_gemm<true,  false, false>,
                         cudaFuncAttributeMaxDynamicSharedMemorySize, SMEM_TOTAL);

    // fp32 -> half staging
    conv_f2h<<<M * D / 1024, 256>>>(x,  xh,  M * D);
    conv_f2h<<<D * D / 1024, 256>>>(Wq, Wqh, D * D);
    conv_f2h<<<D * D / 1024, 256>>>(Wk, Wkh, D * D);
    conv_f2h<<<D * D / 1024, 256>>>(Wv, Wvh, D * D);
    conv_f2h<<<D * D / 1024, 256>>>(Wo, Woh, D * D);

    dim3 th(256);
    dim3 gp(D / BN, M / BM, 1);
    dim3 gs(T / BN, T / BM, B);
    dim3 gv(D / BN, T / BM, B);

    // projections (half out, +bias)
    tc_gemm<true, false, true><<<gp, th, SMEM_TOTAL>>>(xh, Wqh, bq, Qh, M, D, D, 1.0f, 0, 0, 0);
    tc_gemm<true, false, true><<<gp, th, SMEM_TOTAL>>>(xh, Wkh, bk, Kh, M, D, D, 1.0f, 0, 0, 0);
    tc_gemm<true, false, true><<<gp, th, SMEM_TOTAL>>>(xh, Wvh, bv, Vh, M, D, D, 1.0f, 0, 0, 0);

    transpose_h<<<dim3(D / 32, T / 32, B), 256>>>(Vh, Vth);

    // scores (fp32 out, scaled)
    tc_gemm<false, true, false><<<gs, th, SMEM_TOTAL>>>(Qh, Kh, nullptr, S, T, T, D, scale,
                                                        sTD, sTD, sTT);
    softmax_row<<<B * T, 256>>>(S, Ph, T);

    // O = P @ V (half out)
    tc_gemm<false, false, true><<<gv, th, SMEM_TOTAL>>>(Ph, Vth, nullptr, Oh, T, D, T, 1.0f,
                                                        sTT, sTD, sTD);

    // out = O @ Wo^T + bo (fp32 out)
    tc_gemm<true, false, false><<<gp, th, SMEM_TOTAL>>>(Oh, Woh, bo, out, M, D, D, 1.0f, 0, 0, 0);
}

// round 5
// speedup vs baseline: 6.9312x; 1.0165x over previous
#include <cuda_runtime.h>
#include <cuda_fp16.h>
#include <cstdint>
#include <math.h>

// ------------------------------ scratch ------------------------------------
__device__ __half g_xh [8192 * 1024];
__device__ __half g_Wqh[1024 * 1024];
__device__ __half g_Wkh[1024 * 1024];
__device__ __half g_Wvh[1024 * 1024];
__device__ __half g_Woh[1024 * 1024];
__device__ __half g_Qh [8192 * 1024];
__device__ __half g_Kh [8192 * 1024];
__device__ __half g_Vh [8192 * 1024];
__device__ __half g_Vth[8192 * 1024];
__device__ __half g_Oh [8192 * 1024];
__device__ __half g_Ph [4LL * 2048 * 2048];
__device__ float  g_S  [4LL * 2048 * 2048];

// ------------------------------ helpers ------------------------------------
__device__ __forceinline__ uint32_t smem_u32(const void* p) {
    uint32_t a;
    asm("{ .reg .u64 t; cvta.to.shared.u64 t, %1; cvt.u32.u64 %0, t; }"
        : "=r"(a) : "l"(p));
    return a;
}
__device__ __forceinline__ void ldsm4(uint32_t& r0, uint32_t& r1,
                                      uint32_t& r2, uint32_t& r3, uint32_t a) {
    asm volatile("ldmatrix.sync.aligned.m8n8.x4.shared.b16 {%0,%1,%2,%3}, [%4];"
                 : "=r"(r0), "=r"(r1), "=r"(r2), "=r"(r3) : "r"(a));
}
__device__ __forceinline__ void mma_f16(float* d, const uint32_t* a,
                                        const uint32_t* b) {
    asm volatile(
        "mma.sync.aligned.m16n8k16.row.col.f32.f16.f16.f32 "
        "{%0,%1,%2,%3}, {%4,%5,%6,%7}, {%8,%9}, {%0,%1,%2,%3};"
        : "+f"(d[0]), "+f"(d[1]), "+f"(d[2]), "+f"(d[3])
        : "r"(a[0]), "r"(a[1]), "r"(a[2]), "r"(a[3]), "r"(b[0]), "r"(b[1]));
}
#define CP_ASYNC16(s, g) \
    asm volatile("cp.async.cg.shared.global [%0], [%1], 16;" :: "r"(s), "l"(g))
#define CP_COMMIT()  asm volatile("cp.async.commit_group;" ::: "memory")
#define CP_WAIT1()   asm volatile("cp.async.wait_group 1;" ::: "memory")

// ------------------------------ GEMM ---------------------------------------
// C[M,N] = A[M,K] @ B[N,K]^T   (half inputs, fp16 MMA, fp32 accumulate)
// Block tile 128x256, BK=64, 3-stage cp.async; 8 warps (2m x 4n), warp 64x64.
static constexpr int BM = 128, BN = 256, BK = 64, STAGES = 3;
static constexpr int A_BYTES     = BM * BK * 2;            // 16384
static constexpr int B_BYTES     = BN * BK * 2;            // 32768
static constexpr int STAGE_BYTES = A_BYTES + B_BYTES;      // 49152
static constexpr int SMEM_TOTAL  = STAGES * STAGE_BYTES;   // 147456

// swizzled byte offset of (row, 16B-quad q) in a [rows][64 halves] tile
__device__ __forceinline__ uint32_t swz(int r, int q) {
    return (uint32_t)(r * 128 + ((q ^ (r & 7)) << 4));
}

// OUTH: store C as half; otherwise float.
template <bool BIAS, bool SCALE, bool OUTH>
__global__ __launch_bounds__(256, 1) void tc_gemm(
    const __half* __restrict__ A, const __half* __restrict__ Bm,
    const float* __restrict__ bias, void* __restrict__ Cv,
    int M, int N, int K, float scale,
    long long sA, long long sB, long long sC)
{
    extern __shared__ __align__(1024) char smem[];
    const uint32_t sb = smem_u32(smem);

    const int tid  = threadIdx.x;
    const int lane = tid & 31;
    const int wid  = tid >> 5;
    const int wm   = (wid >> 2) * 64;   // 0 or 64
    const int wn   = (wid & 3) * 64;    // 0,64,128,192

    const long long bz = blockIdx.z;
    A  += bz * sA;
    Bm += bz * sB;
    const int m0 = blockIdx.y * BM;
    const int n0 = blockIdx.x * BN;
    const int nchunks = K / BK;

    const int midx = lane >> 3, l7 = lane & 7;
    int aR[4];
#pragma unroll
    for (int mi = 0; mi < 4; mi++) aR[mi] = wm + mi * 16 + ((midx & 1) << 3) + l7;
    const int aKH = midx >> 1;
    int bR[4];
#pragma unroll
    for (int n2 = 0; n2 < 4; n2++) bR[n2] = wn + n2 * 16 + ((midx >> 1) << 3) + l7;
    const int bKH = midx & 1;

    float acc[4][8][4];
#pragma unroll
    for (int mi = 0; mi < 4; mi++)
#pragma unroll
        for (int ni = 0; ni < 8; ni++)
#pragma unroll
            for (int j = 0; j < 4; j++) acc[mi][ni][j] = 0.0f;

    auto issue = [&](int c) {
        if (c < nchunks) {
            const int s = c % STAGES;
            const uint32_t As = sb + s * STAGE_BYTES;
            const uint32_t Bs = As + A_BYTES;
            const int k0 = c * BK;
#pragma unroll
            for (int i = tid; i < 3072; i += 256) {
                if (i < 1024) {
                    const int r = i >> 3, q = i & 7;
                    CP_ASYNC16(As + swz(r, q),
                               A + (long long)(m0 + r) * K + k0 + q * 8);
                } else {
                    const int idx = i - 1024;
                    const int r = idx >> 3, q = idx & 7;
                    CP_ASYNC16(Bs + swz(r, q),
                               Bm + (long long)(n0 + r) * K + k0 + q * 8);
                }
            }
        }
        CP_COMMIT();
    };

    issue(0);
    issue(1);

    for (int c = 0; c < nchunks; c++) {
        CP_WAIT1();
        __syncthreads();
        issue(c + 2);

        const int s = c % STAGES;
        const uint32_t As = sb + s * STAGE_BYTES;
        const uint32_t Bs = As + A_BYTES;

#pragma unroll
        for (int kk = 0; kk < 4; kk++) {        // 4 x k16
            uint32_t aF[4][4], bF[8][2];
#pragma unroll
            for (int mi = 0; mi < 4; mi++)
                ldsm4(aF[mi][0], aF[mi][1], aF[mi][2], aF[mi][3],
                      As + swz(aR[mi], kk * 2 + aKH));
#pragma unroll
            for (int n2 = 0; n2 < 4; n2++) {
                uint32_t r0, r1, r2, r3;
                ldsm4(r0, r1, r2, r3, Bs + swz(bR[n2], kk * 2 + bKH));
                bF[n2 * 2 + 0][0] = r0;
                bF[n2 * 2 + 0][1] = r1;
                bF[n2 * 2 + 1][0] = r2;
                bF[n2 * 2 + 1][1] = r3;
            }
#pragma unroll
            for (int mi = 0; mi < 4; mi++)
#pragma unroll
                for (int ni = 0; ni < 8; ni++)
                    mma_f16(acc[mi][ni], aF[mi], bF[ni]);
        }
    }

    // ------------------ epilogue ------------------
    const int crow = lane >> 2;
    const int ccol = (lane & 3) * 2;
#pragma unroll
    for (int mi = 0; mi < 4; mi++) {
#pragma unroll
        for (int ni = 0; ni < 8; ni++) {
            const int col = n0 + wn + ni * 8 + ccol;
            float2 b2 = make_float2(0.f, 0.f);
            if (BIAS) b2 = *(const float2*)&bias[col];
#pragma unroll
            for (int h = 0; h < 2; h++) {
                const int row = m0 + wm + mi * 16 + crow + h * 8;
                float vx = acc[mi][ni][h * 2 + 0];
                float vy = acc[mi][ni][h * 2 + 1];
                if (SCALE) { vx *= scale; vy *= scale; }
                if (BIAS)  { vx += b2.x;  vy += b2.y; }
                if (OUTH) {
                    __half2* C = (__half2*)((__half*)Cv + bz * sC);
                    C[((long long)row * N + col) >> 1] = __floats2half2_rn(vx, vy);
                } else {
                    float* C = (float*)Cv + bz * sC;
                    *(float2*)&C[(long long)row * N + col] = make_float2(vx, vy);
                }
            }
        }
    }
}

// ------------------------------ conversions --------------------------------
__global__ __launch_bounds__(256) void conv_f2h(const float* __restrict__ s,
                                                __half* __restrict__ d, int n)
{
    int i = (blockIdx.x * 256 + threadIdx.x) * 4;
    if (i < n) {
        float4 v = *(const float4*)&s[i];
        *(__half2*)&d[i]     = __floats2half2_rn(v.x, v.y);
        *(__half2*)&d[i + 2] = __floats2half2_rn(v.z, v.w);
    }
}

// Vth[b][d][t] = Vh[b][t][d]
__global__ __launch_bounds__(256) void transpose_h(
    const __half* __restrict__ V, __half* __restrict__ Vt)
{
    __shared__ __half tile[32][33];
    const long long b = blockIdx.z;
    const __half* src = V + b * 2048LL * 1024;
    __half* dst = Vt + b * 2048LL * 1024;
    const int x0 = blockIdx.x * 32;   // d
    const int y0 = blockIdx.y * 32;   // t
    const int tx = threadIdx.x & 31;
    const int ty = threadIdx.x >> 5;
#pragma unroll
    for (int i = 0; i < 32; i += 8)
        tile[ty + i][tx] = src[(long long)(y0 + ty + i) * 1024 + x0 + tx];
    __syncthreads();
#pragma unroll
    for (int i = 0; i < 32; i += 8)
        dst[(long long)(x0 + ty + i) * 2048 + y0 + tx] = tile[tx][ty + i];
}

// ------------------------------ softmax ------------------------------------
__global__ __launch_bounds__(256) void softmax_row(
    const float* __restrict__ S, __half* __restrict__ P, int T)
{
    __shared__ float buf[2048];
    __shared__ float red[256];
    const long long row = blockIdx.x;
    const float* r = S + row * T;
    __half* o = P + row * T;
    const int t = threadIdx.x;

    float m = -1e30f;
    for (int i = t * 4; i < T; i += 1024) {
        float4 v = *(const float4*)&r[i];
        *(float4*)&buf[i] = v;
        m = fmaxf(m, fmaxf(fmaxf(v.x, v.y), fmaxf(v.z, v.w)));
    }
    red[t] = m;
    __syncthreads();
    for (int s = 128; s > 0; s >>= 1) {
        if (t < s) red[t] = fmaxf(red[t], red[t + s]);
        __syncthreads();
    }
    m = red[0];
    __syncthreads();

    float sum = 0.0f;
    for (int i = t * 4; i < T; i += 1024) {
        float4 v = *(const float4*)&buf[i];
        v.x = expf(v.x - m); v.y = expf(v.y - m);
        v.z = expf(v.z - m); v.w = expf(v.w - m);
        sum += v.x + v.y + v.z + v.w;
        *(float4*)&buf[i] = v;
    }
    red[t] = sum;
    __syncthreads();
    for (int s = 128; s > 0; s >>= 1) {
        if (t < s) red[t] += red[t + s];
        __syncthreads();
    }
    const float inv = 1.0f / red[0];
    for (int i = t * 4; i < T; i += 1024) {
        float4 v = *(const float4*)&buf[i];
        *(__half2*)&o[i]     = __floats2half2_rn(v.x * inv, v.y * inv);
        *(__half2*)&o[i + 2] = __floats2half2_rn(v.z * inv, v.w * inv);
    }
}

// ------------------------------ launch -------------------------------------
extern "C" void kernel_launch(void* const* d_in, const int* in_sizes, int n_in,
                              void* d_out, int out_size)
{
    (void)in_sizes; (void)n_in; (void)out_size;
    const float* x  = (const float*)d_in[0];
    const float* Wq = (const float*)d_in[1];
    const float* bq = (const float*)d_in[2];
    const float* Wk = (const float*)d_in[3];
    const float* bk = (const float*)d_in[4];
    const float* Wv = (const float*)d_in[5];
    const float* bv = (const float*)d_in[6];
    const float* Wo = (const float*)d_in[7];
    const float* bo = (const float*)d_in[8];
    float* out = (float*)d_out;

    __half *xh, *Wqh, *Wkh, *Wvh, *Woh, *Qh, *Kh, *Vh, *Vth, *Oh, *Ph;
    float* S;
    cudaGetSymbolAddress((void**)&xh,  g_xh);
    cudaGetSymbolAddress((void**)&Wqh, g_Wqh);
    cudaGetSymbolAddress((void**)&Wkh, g_Wkh);
    cudaGetSymbolAddress((void**)&Wvh, g_Wvh);
    cudaGetSymbolAddress((void**)&Woh, g_Woh);
    cudaGetSymbolAddress((void**)&Qh,  g_Qh);
    cudaGetSymbolAddress((void**)&Kh,  g_Kh);
    cudaGetSymbolAddress((void**)&Vh,  g_Vh);
    cudaGetSymbolAddress((void**)&Vth, g_Vth);
    cudaGetSymbolAddress((void**)&Oh,  g_Oh);
    cudaGetSymbolAddress((void**)&Ph,  g_Ph);
    cudaGetSymbolAddress((void**)&S,   g_S);

    const int B = 4, T = 2048, D = 1024;
    const int M = B * T;
    const float scale = 0.03125f;   // 1/sqrt(1024)
    const long long sTD = (long long)T * D;
    const long long sTT = (long long)T * T;

    cudaFuncSetAttribute(tc_gemm<true,  false, true >,
                         cudaFuncAttributeMaxDynamicSharedMemorySize, SMEM_TOTAL);
    cudaFuncSetAttribute(tc_gemm<false, true,  false>,
                         cudaFuncAttributeMaxDynamicSharedMemorySize, SMEM_TOTAL);
    cudaFuncSetAttribute(tc_gemm<false, false, true >,
                         cudaFuncAttributeMaxDynamicSharedMemorySize, SMEM_TOTAL);
    cudaFuncSetAttribute(tc_gemm<true,  false, false>,
                         cudaFuncAttributeMaxDynamicSharedMemorySize, SMEM_TOTAL);

    // fp32 -> half staging
    conv_f2h<<<M * D / 1024, 256>>>(x,  xh,  M * D);
    conv_f2h<<<D * D / 1024, 256>>>(Wq, Wqh, D * D);
    conv_f2h<<<D * D / 1024, 256>>>(Wk, Wkh, D * D);
    conv_f2h<<<D * D / 1024, 256>>>(Wv, Wvh, D * D);
    conv_f2h<<<D * D / 1024, 256>>>(Wo, Woh, D * D);

    dim3 th(256);
    dim3 gp(D / BN, M / BM, 1);     // 4 x 64      projections / output
    dim3 gs(T / BN, T / BM, B);     // 8 x 16 x 4  scores
    dim3 gv(D / BN, T / BM, B);     // 4 x 16 x 4  P @ V

    // projections (half out, +bias)
    tc_gemm<true, false, true><<<gp, th, SMEM_TOTAL>>>(xh, Wqh, bq, Qh, M, D, D, 1.0f, 0, 0, 0);
    tc_gemm<true, false, true><<<gp, th, SMEM_TOTAL>>>(xh, Wkh, bk, Kh, M, D, D, 1.0f, 0, 0, 0);
    tc_gemm<true, false, true><<<gp, th, SMEM_TOTAL>>>(xh, Wvh, bv, Vh, M, D, D, 1.0f, 0, 0, 0);

    transpose_h<<<dim3(D / 32, T / 32, B), 256>>>(Vh, Vth);

    // scores (fp32 out, scaled)
    tc_gemm<false, true, false><<<gs, th, SMEM_TOTAL>>>(Qh, Kh, nullptr, S, T, T, D, scale,
                                                        sTD, sTD, sTT);
    softmax_row<<<B * T, 256>>>(S, Ph, T);

    // O = P @ V (half out)
    tc_gemm<false, false, true><<<gv, th, SMEM_TOTAL>>>(Ph, Vth, nullptr, Oh, T, D, T, 1.0f,
                                                        sTT, sTD, sTD);

    // out = O @ Wo^T + bo (fp32 out)
    tc_gemm<true, false, false><<<gp, th, SMEM_TOTAL>>>(Oh, Woh, bo, out, M, D, D, 1.0f, 0, 0, 0);
}